// round 2
// baseline (speedup 1.0000x reference)
#include <cuda_runtime.h>

#define N_NODES 100000
#define N_EDGES 1600000
#define F 128
#define ALPHA 0.2f
#define LN_EPS 1e-5f

// ---------------- device scratch (static, allowed) ----------------
__device__ float    g_h[(size_t)N_NODES * F];
__device__ float    g_ssrc[N_NODES];
__device__ float    g_sdst[N_NODES];
__device__ float    g_el[N_EDGES];          // leaky-relu'd edge scores
__device__ int      g_hist[N_NODES];
__device__ int      g_cursor[N_NODES];
__device__ int      g_rowstart[N_NODES + 1];
__device__ int      g_sorted_dst[N_EDGES];
__device__ float    g_sorted_e[N_EDGES];
__device__ unsigned g_gmaxk;

// ordered-uint encoding for float atomicMax
__device__ __forceinline__ unsigned f2o(float f) {
    unsigned b = __float_as_uint(f);
    return (b & 0x80000000u) ? ~b : (b | 0x80000000u);
}
__device__ __forceinline__ float o2f(unsigned u) {
    return (u & 0x80000000u) ? __uint_as_float(u & 0x7FFFFFFFu)
                             : __uint_as_float(~u);
}

// ---------------- K0: init counters ----------------
__global__ void init_kernel() {
    int i = blockIdx.x * blockDim.x + threadIdx.x;
    if (i < N_NODES) { g_hist[i] = 0; g_cursor[i] = 0; }
    if (i == 0) g_gmaxk = f2o(-3.4e38f);
}

// ---------------- K1: h = x@W + bias ; s_src = h@a[:F]; s_dst = h@a[F:] ----
// One warp computes 4 rows; lane owns 4 output columns.
__global__ void gemm_kernel(const float* __restrict__ x,
                            const float* __restrict__ W,
                            const float* __restrict__ a,
                            const float* __restrict__ bias) {
    int warp = blockIdx.x * (blockDim.x >> 5) + (threadIdx.x >> 5);
    int lane = threadIdx.x & 31;
    int r0 = warp * 4;
    if (r0 >= N_NODES) return;
    int c = lane * 4;

    float4 b4 = *(const float4*)&bias[c];
    float4 acc[4];
#pragma unroll
    for (int i = 0; i < 4; i++) acc[i] = b4;

#pragma unroll 4
    for (int k = 0; k < F; k += 4) {
        float4 w0 = *(const float4*)&W[(k + 0) * F + c];
        float4 w1 = *(const float4*)&W[(k + 1) * F + c];
        float4 w2 = *(const float4*)&W[(k + 2) * F + c];
        float4 w3 = *(const float4*)&W[(k + 3) * F + c];
#pragma unroll
        for (int i = 0; i < 4; i++) {
            float4 xv = *(const float4*)&x[(r0 + i) * F + k];
            acc[i].x += xv.x * w0.x + xv.y * w1.x + xv.z * w2.x + xv.w * w3.x;
            acc[i].y += xv.x * w0.y + xv.y * w1.y + xv.z * w2.y + xv.w * w3.y;
            acc[i].z += xv.x * w0.z + xv.y * w1.z + xv.z * w2.z + xv.w * w3.z;
            acc[i].w += xv.x * w0.w + xv.y * w1.w + xv.z * w2.w + xv.w * w3.w;
        }
    }

    float4 as = *(const float4*)&a[c];
    float4 ad = *(const float4*)&a[F + c];
#pragma unroll
    for (int i = 0; i < 4; i++) {
        *(float4*)&g_h[(r0 + i) * F + c] = acc[i];
        float ps = acc[i].x * as.x + acc[i].y * as.y + acc[i].z * as.z + acc[i].w * as.w;
        float pd = acc[i].x * ad.x + acc[i].y * ad.y + acc[i].z * ad.z + acc[i].w * ad.w;
#pragma unroll
        for (int o = 16; o > 0; o >>= 1) {
            ps += __shfl_xor_sync(0xFFFFFFFFu, ps, o);
            pd += __shfl_xor_sync(0xFFFFFFFFu, pd, o);
        }
        if (lane == 0) { g_ssrc[r0 + i] = ps; g_sdst[r0 + i] = pd; }
    }
}

// ---------------- K2: per-edge leaky score, global max, degree histogram ---
__global__ void edge_kernel(const int* __restrict__ edge) {
    int i = blockIdx.x * blockDim.x + threadIdx.x;
    float lm = -3.4e38f;
    if (i < N_EDGES) {
        int s = edge[i];
        int d = edge[N_EDGES + i];
        float v = g_ssrc[s] + g_sdst[d];
        float l = v > 0.f ? v : ALPHA * v;
        g_el[i] = lm = l;
        atomicAdd(&g_hist[s], 1);
    }
#pragma unroll
    for (int o = 16; o > 0; o >>= 1)
        lm = fmaxf(lm, __shfl_xor_sync(0xFFFFFFFFu, lm, o));
    if ((threadIdx.x & 31) == 0) atomicMax(&g_gmaxk, f2o(lm));
}

// ---------------- K3: single-block exclusive scan (hist -> rowstart) -------
__global__ void scan_kernel() {
    __shared__ int wsum[32];
    __shared__ int s_carry;
    int tid = threadIdx.x, lane = tid & 31, wid = tid >> 5;
    int nwarp = blockDim.x >> 5;
    if (tid == 0) s_carry = 0;
    __syncthreads();
    for (int base = 0; base < N_NODES; base += blockDim.x) {
        int i = base + tid;
        int v = (i < N_NODES) ? g_hist[i] : 0;
        int x = v;
#pragma unroll
        for (int o = 1; o < 32; o <<= 1) {
            int y = __shfl_up_sync(0xFFFFFFFFu, x, o);
            if (lane >= o) x += y;
        }
        if (lane == 31) wsum[wid] = x;
        __syncthreads();
        if (wid == 0) {
            int t = (lane < nwarp) ? wsum[lane] : 0;
#pragma unroll
            for (int o = 1; o < 32; o <<= 1) {
                int y = __shfl_up_sync(0xFFFFFFFFu, t, o);
                if (lane >= o) t += y;
            }
            wsum[lane] = t;
        }
        __syncthreads();
        int woff = (wid > 0) ? wsum[wid - 1] : 0;
        int incl = x + woff;
        int carry = s_carry;
        if (i < N_NODES) g_rowstart[i] = carry + incl - v;
        __syncthreads();
        if (tid == blockDim.x - 1) s_carry = carry + incl;
        __syncthreads();
    }
    if (tid == 0) g_rowstart[N_NODES] = s_carry;
}

// ---------------- K4: scatter edges into CSR order -------------------------
__global__ void scatter_kernel(const int* __restrict__ edge) {
    int i = blockIdx.x * blockDim.x + threadIdx.x;
    if (i >= N_EDGES) return;
    int s = edge[i];
    int pos = g_rowstart[s] + atomicAdd(&g_cursor[s], 1);
    g_sorted_dst[pos] = edge[N_EDGES + i];
    g_sorted_e[pos] = g_el[i];
}

// ---------------- K5: warp-per-node aggregate + residual + LN + ELU --------
__global__ void node_kernel(const float* __restrict__ x,
                            const float* __restrict__ gamma,
                            const float* __restrict__ beta,
                            float* __restrict__ out) {
    int node = blockIdx.x * (blockDim.x >> 5) + (threadIdx.x >> 5);
    if (node >= N_NODES) return;
    int lane = threadIdx.x & 31;
    int c = lane * 4;

    float M = o2f(g_gmaxk);
    int s = g_rowstart[node];
    int e = g_rowstart[node + 1];

    float4 acc = make_float4(0.f, 0.f, 0.f, 0.f);
    float rowsum = 0.f;
    for (int j = s; j < e; j++) {
        int d = g_sorted_dst[j];
        float w = __expf(g_sorted_e[j] - M);
        rowsum += w;
        float4 hv = *(const float4*)&g_h[d * F + c];
        acc.x += w * hv.x; acc.y += w * hv.y;
        acc.z += w * hv.z; acc.w += w * hv.w;
    }
    float inv = 1.f / (rowsum + 1e-8f);
    float4 xv = *(const float4*)&x[node * F + c];
    float4 hp;
    hp.x = acc.x * inv + xv.x;
    hp.y = acc.y * inv + xv.y;
    hp.z = acc.z * inv + xv.z;
    hp.w = acc.w * inv + xv.w;

    float s1 = hp.x + hp.y + hp.z + hp.w;
    float s2 = hp.x * hp.x + hp.y * hp.y + hp.z * hp.z + hp.w * hp.w;
#pragma unroll
    for (int o = 16; o > 0; o >>= 1) {
        s1 += __shfl_xor_sync(0xFFFFFFFFu, s1, o);
        s2 += __shfl_xor_sync(0xFFFFFFFFu, s2, o);
    }
    float mean = s1 * (1.f / F);
    float var = s2 * (1.f / F) - mean * mean;
    float rstd = rsqrtf(var + LN_EPS);

    float4 g = *(const float4*)&gamma[c];
    float4 b = *(const float4*)&beta[c];
    float4 y;
    y.x = (hp.x - mean) * rstd * g.x + b.x;
    y.y = (hp.y - mean) * rstd * g.y + b.y;
    y.z = (hp.z - mean) * rstd * g.z + b.z;
    y.w = (hp.w - mean) * rstd * g.w + b.w;
    // ELU (alpha = 1)
    y.x = y.x > 0.f ? y.x : (__expf(y.x) - 1.f);
    y.y = y.y > 0.f ? y.y : (__expf(y.y) - 1.f);
    y.z = y.z > 0.f ? y.z : (__expf(y.z) - 1.f);
    y.w = y.w > 0.f ? y.w : (__expf(y.w) - 1.f);

    *(float4*)&out[node * F + c] = y;
}

// ---------------- launch ----------------
extern "C" void kernel_launch(void* const* d_in, const int* in_sizes, int n_in,
                              void* d_out, int out_size) {
    const float* x     = (const float*)d_in[0];
    const int*   edge  = (const int*)d_in[1];
    const float* W     = (const float*)d_in[2];
    const float* a     = (const float*)d_in[3];
    const float* bias  = (const float*)d_in[4];
    const float* gamma = (const float*)d_in[5];
    const float* beta  = (const float*)d_in[6];
    float*       out   = (float*)d_out;

    init_kernel<<<(N_NODES + 255) / 256, 256>>>();
    gemm_kernel<<<(N_NODES / 4 + 7) / 8, 256>>>(x, W, a, bias);
    edge_kernel<<<(N_EDGES + 255) / 256, 256>>>(edge);
    scan_kernel<<<1, 1024>>>();
    scatter_kernel<<<(N_EDGES + 255) / 256, 256>>>(edge);
    node_kernel<<<(N_NODES + 7) / 8, 256>>>(x, gamma, beta, out);
}

// round 4
// speedup vs baseline: 1.2634x; 1.2634x over previous
#include <cuda_runtime.h>

#define N_NODES 100000
#define N_EDGES 1600000
#define F 128
#define ALPHA 0.2f
#define LN_EPS 1e-5f

#define SCAN_TPB 512
#define SCAN_NBLK ((N_NODES + SCAN_TPB - 1) / SCAN_TPB)   // 196
#define SCAN_NW (SCAN_TPB / 32)                            // 16

// ---------------- device scratch (static, allowed) ----------------
__device__ float    g_h[(size_t)N_NODES * F];
__device__ float    g_ssrc[N_NODES];
__device__ float    g_sdst[N_NODES];
__device__ float    g_el[N_EDGES];          // leaky-relu'd edge scores
__device__ int      g_hist[N_NODES];
__device__ int      g_cursor[N_NODES];
__device__ int      g_rowstart[N_NODES + 1];
__device__ int      g_sorted_dst[N_EDGES];
__device__ float    g_sorted_e[N_EDGES];
__device__ int      g_blocksum[SCAN_NBLK];
__device__ int      g_blockoff[SCAN_NBLK];
__device__ unsigned g_gmaxk;

// ordered-uint encoding for float atomicMax
__device__ __forceinline__ unsigned f2o(float f) {
    unsigned b = __float_as_uint(f);
    return (b & 0x80000000u) ? ~b : (b | 0x80000000u);
}
__device__ __forceinline__ float o2f(unsigned u) {
    return (u & 0x80000000u) ? __uint_as_float(u & 0x7FFFFFFFu)
                             : __uint_as_float(~u);
}

// ---------------- K0: init counters ----------------
__global__ void init_kernel() {
    int i = blockIdx.x * blockDim.x + threadIdx.x;
    if (i < N_NODES) { g_hist[i] = 0; g_cursor[i] = 0; }
    if (i == 0) g_gmaxk = f2o(-3.4e38f);
}

// ---------------- K1: h = x@W + bias ; s_src = h@a[:F]; s_dst = h@a[F:] ----
// One warp computes 4 rows; lane owns 4 output columns.
__global__ void gemm_kernel(const float* __restrict__ x,
                            const float* __restrict__ W,
                            const float* __restrict__ a,
                            const float* __restrict__ bias) {
    int warp = blockIdx.x * (blockDim.x >> 5) + (threadIdx.x >> 5);
    int lane = threadIdx.x & 31;
    int r0 = warp * 4;
    if (r0 >= N_NODES) return;
    int c = lane * 4;

    float4 b4 = *(const float4*)&bias[c];
    float4 acc[4];
#pragma unroll
    for (int i = 0; i < 4; i++) acc[i] = b4;

#pragma unroll 4
    for (int k = 0; k < F; k += 4) {
        float4 w0 = *(const float4*)&W[(k + 0) * F + c];
        float4 w1 = *(const float4*)&W[(k + 1) * F + c];
        float4 w2 = *(const float4*)&W[(k + 2) * F + c];
        float4 w3 = *(const float4*)&W[(k + 3) * F + c];
#pragma unroll
        for (int i = 0; i < 4; i++) {
            float4 xv = *(const float4*)&x[(r0 + i) * F + k];
            acc[i].x += xv.x * w0.x + xv.y * w1.x + xv.z * w2.x + xv.w * w3.x;
            acc[i].y += xv.x * w0.y + xv.y * w1.y + xv.z * w2.y + xv.w * w3.y;
            acc[i].z += xv.x * w0.z + xv.y * w1.z + xv.z * w2.z + xv.w * w3.z;
            acc[i].w += xv.x * w0.w + xv.y * w1.w + xv.z * w2.w + xv.w * w3.w;
        }
    }

    float4 as = *(const float4*)&a[c];
    float4 ad = *(const float4*)&a[F + c];
#pragma unroll
    for (int i = 0; i < 4; i++) {
        *(float4*)&g_h[(r0 + i) * F + c] = acc[i];
        float ps = acc[i].x * as.x + acc[i].y * as.y + acc[i].z * as.z + acc[i].w * as.w;
        float pd = acc[i].x * ad.x + acc[i].y * ad.y + acc[i].z * ad.z + acc[i].w * ad.w;
#pragma unroll
        for (int o = 16; o > 0; o >>= 1) {
            ps += __shfl_xor_sync(0xFFFFFFFFu, ps, o);
            pd += __shfl_xor_sync(0xFFFFFFFFu, pd, o);
        }
        if (lane == 0) { g_ssrc[r0 + i] = ps; g_sdst[r0 + i] = pd; }
    }
}

// ---------------- K2: per-edge leaky score, global max, degree histogram ---
__global__ void edge_kernel(const int* __restrict__ edge) {
    int i = blockIdx.x * blockDim.x + threadIdx.x;
    float lm = -3.4e38f;
    if (i < N_EDGES) {
        int s = edge[i];
        int d = edge[N_EDGES + i];
        float v = g_ssrc[s] + g_sdst[d];
        float l = v > 0.f ? v : ALPHA * v;
        g_el[i] = lm = l;
        atomicAdd(&g_hist[s], 1);
    }
#pragma unroll
    for (int o = 16; o > 0; o >>= 1)
        lm = fmaxf(lm, __shfl_xor_sync(0xFFFFFFFFu, lm, o));
    if ((threadIdx.x & 31) == 0) atomicMax(&g_gmaxk, f2o(lm));
}

// ---------------- K3a: per-block sums of hist ------------------------------
__global__ void scan_sums_kernel() {
    __shared__ int wsum[SCAN_NW];
    int tid = threadIdx.x;
    int i = blockIdx.x * SCAN_TPB + tid;
    int v = (i < N_NODES) ? g_hist[i] : 0;
    int s = v;
#pragma unroll
    for (int o = 16; o > 0; o >>= 1) s += __shfl_xor_sync(0xFFFFFFFFu, s, o);
    if ((tid & 31) == 0) wsum[tid >> 5] = s;
    __syncthreads();
    if (tid < 32) {   // full warp executes the shuffles
        int t = (tid < SCAN_NW) ? wsum[tid] : 0;
#pragma unroll
        for (int o = 16; o > 0; o >>= 1)
            t += __shfl_xor_sync(0xFFFFFFFFu, t, o);
        if (tid == 0) g_blocksum[blockIdx.x] = t;
    }
}

// ---------------- K3b: single-block exclusive scan of 196 block sums -------
__global__ void scan_offsets_kernel() {
    __shared__ int wsum[8];
    int tid = threadIdx.x;   // 256 threads >= SCAN_NBLK
    int lane = tid & 31, wid = tid >> 5;
    int v = (tid < SCAN_NBLK) ? g_blocksum[tid] : 0;
    int x = v;
#pragma unroll
    for (int o = 1; o < 32; o <<= 1) {
        int y = __shfl_up_sync(0xFFFFFFFFu, x, o);
        if (lane >= o) x += y;
    }
    if (lane == 31) wsum[wid] = x;
    __syncthreads();
    if (wid == 0) {   // full warp executes the shuffles
        int t = (lane < 8) ? wsum[lane] : 0;
#pragma unroll
        for (int o = 1; o < 8; o <<= 1) {
            int y = __shfl_up_sync(0xFFFFFFFFu, t, o);
            if (lane >= o) t += y;
        }
        if (lane < 8) wsum[lane] = t;
    }
    __syncthreads();
    int incl = x + ((wid > 0) ? wsum[wid - 1] : 0);
    if (tid < SCAN_NBLK) g_blockoff[tid] = incl - v;
    if (tid == SCAN_NBLK - 1) g_rowstart[N_NODES] = incl;
}

// ---------------- K3c: per-block local exclusive scan + offset -------------
__global__ void scan_apply_kernel() {
    __shared__ int wsum[SCAN_NW];
    int tid = threadIdx.x, lane = tid & 31, wid = tid >> 5;
    int i = blockIdx.x * SCAN_TPB + tid;
    int v = (i < N_NODES) ? g_hist[i] : 0;
    int x = v;
#pragma unroll
    for (int o = 1; o < 32; o <<= 1) {
        int y = __shfl_up_sync(0xFFFFFFFFu, x, o);
        if (lane >= o) x += y;
    }
    if (lane == 31) wsum[wid] = x;
    __syncthreads();
    if (wid == 0) {   // full warp executes the shuffles
        int t = (lane < SCAN_NW) ? wsum[lane] : 0;
#pragma unroll
        for (int o = 1; o < SCAN_NW; o <<= 1) {
            int y = __shfl_up_sync(0xFFFFFFFFu, t, o);
            if (lane >= o) t += y;
        }
        if (lane < SCAN_NW) wsum[lane] = t;
    }
    __syncthreads();
    int incl = x + ((wid > 0) ? wsum[wid - 1] : 0);
    if (i < N_NODES) g_rowstart[i] = g_blockoff[blockIdx.x] + incl - v;
}

// ---------------- K4: scatter edges into CSR order -------------------------
__global__ void scatter_kernel(const int* __restrict__ edge) {
    int i = blockIdx.x * blockDim.x + threadIdx.x;
    if (i >= N_EDGES) return;
    int s = edge[i];
    int pos = g_rowstart[s] + atomicAdd(&g_cursor[s], 1);
    g_sorted_dst[pos] = edge[N_EDGES + i];
    g_sorted_e[pos] = g_el[i];
}

// ---------------- K5: warp-per-node aggregate + residual + LN + ELU --------
__global__ void node_kernel(const float* __restrict__ x,
                            const float* __restrict__ gamma,
                            const float* __restrict__ beta,
                            float* __restrict__ out) {
    int node = blockIdx.x * (blockDim.x >> 5) + (threadIdx.x >> 5);
    if (node >= N_NODES) return;
    int lane = threadIdx.x & 31;
    int c = lane * 4;

    float M = o2f(g_gmaxk);
    int s = g_rowstart[node];
    int e = g_rowstart[node + 1];

    float4 acc = make_float4(0.f, 0.f, 0.f, 0.f);
    float rowsum = 0.f;
    for (int j = s; j < e; j++) {
        int d = g_sorted_dst[j];
        float w = __expf(g_sorted_e[j] - M);
        rowsum += w;
        float4 hv = *(const float4*)&g_h[d * F + c];
        acc.x += w * hv.x; acc.y += w * hv.y;
        acc.z += w * hv.z; acc.w += w * hv.w;
    }
    float inv = 1.f / (rowsum + 1e-8f);
    float4 xv = *(const float4*)&x[node * F + c];
    float4 hp;
    hp.x = acc.x * inv + xv.x;
    hp.y = acc.y * inv + xv.y;
    hp.z = acc.z * inv + xv.z;
    hp.w = acc.w * inv + xv.w;

    float s1 = hp.x + hp.y + hp.z + hp.w;
    float s2 = hp.x * hp.x + hp.y * hp.y + hp.z * hp.z + hp.w * hp.w;
#pragma unroll
    for (int o = 16; o > 0; o >>= 1) {
        s1 += __shfl_xor_sync(0xFFFFFFFFu, s1, o);
        s2 += __shfl_xor_sync(0xFFFFFFFFu, s2, o);
    }
    float mean = s1 * (1.f / F);
    float var = s2 * (1.f / F) - mean * mean;
    float rstd = rsqrtf(var + LN_EPS);

    float4 g = *(const float4*)&gamma[c];
    float4 b = *(const float4*)&beta[c];
    float4 y;
    y.x = (hp.x - mean) * rstd * g.x + b.x;
    y.y = (hp.y - mean) * rstd * g.y + b.y;
    y.z = (hp.z - mean) * rstd * g.z + b.z;
    y.w = (hp.w - mean) * rstd * g.w + b.w;
    // ELU (alpha = 1)
    y.x = y.x > 0.f ? y.x : (__expf(y.x) - 1.f);
    y.y = y.y > 0.f ? y.y : (__expf(y.y) - 1.f);
    y.z = y.z > 0.f ? y.z : (__expf(y.z) - 1.f);
    y.w = y.w > 0.f ? y.w : (__expf(y.w) - 1.f);

    *(float4*)&out[node * F + c] = y;
}

// ---------------- launch ----------------
extern "C" void kernel_launch(void* const* d_in, const int* in_sizes, int n_in,
                              void* d_out, int out_size) {
    const float* x     = (const float*)d_in[0];
    const int*   edge  = (const int*)d_in[1];
    const float* W     = (const float*)d_in[2];
    const float* a     = (const float*)d_in[3];
    const float* bias  = (const float*)d_in[4];
    const float* gamma = (const float*)d_in[5];
    const float* beta  = (const float*)d_in[6];
    float*       out   = (float*)d_out;

    init_kernel<<<(N_NODES + 255) / 256, 256>>>();
    gemm_kernel<<<(N_NODES / 4 + 7) / 8, 256>>>(x, W, a, bias);
    edge_kernel<<<(N_EDGES + 255) / 256, 256>>>(edge);
    scan_sums_kernel<<<SCAN_NBLK, SCAN_TPB>>>();
    scan_offsets_kernel<<<1, 256>>>();
    scan_apply_kernel<<<SCAN_NBLK, SCAN_TPB>>>();
    scatter_kernel<<<(N_EDGES + 255) / 256, 256>>>(edge);
    node_kernel<<<(N_NODES + 7) / 8, 256>>>(x, gamma, beta, out);
}